// round 4
// baseline (speedup 1.0000x reference)
#include <cuda_runtime.h>
#include <cstdint>

#define SQ 2048   // sequence length
#define NB 64     // batch
#define NH 256    // hidden
#define NI 256    // input
#define NO 256    // output

typedef unsigned long long ull;

// ---------------- packed f32x2 helpers ----------------
__device__ __forceinline__ ull f2fma(ull a, ull b, ull c) {
    ull d;
    asm("fma.rn.f32x2 %0, %1, %2, %3;" : "=l"(d) : "l"(a), "l"(b), "l"(c));
    return d;
}
__device__ __forceinline__ ull f2dup(float a) {
    ull d; unsigned ai = __float_as_uint(a);
    asm("mov.b64 %0, {%1, %2};" : "=l"(d) : "r"(ai), "r"(ai));
    return d;
}
__device__ __forceinline__ float f2sum(ull a) {
    unsigned lo, hi;
    asm("mov.b64 {%0, %1}, %2;" : "=r"(lo), "=r"(hi) : "l"(a));
    return __uint_as_float(lo) + __uint_as_float(hi);
}
__device__ __forceinline__ float2 f2unpack(ull a) {
    unsigned lo, hi;
    asm("mov.b64 {%0, %1}, %2;" : "=r"(lo), "=r"(hi) : "l"(a));
    return make_float2(__uint_as_float(lo), __uint_as_float(hi));
}

// ---------------- mbarrier / dsmem helpers ----------------
__device__ __forceinline__ void mbar_init(uint32_t bar, uint32_t cnt) {
    asm volatile("mbarrier.init.shared.b64 [%0], %1;" :: "r"(bar), "r"(cnt) : "memory");
}
__device__ __forceinline__ void mbar_expect_tx(uint32_t bar, uint32_t bytes) {
    asm volatile("mbarrier.arrive.expect_tx.shared.b64 _, [%0], %1;"
                 :: "r"(bar), "r"(bytes) : "memory");
}
__device__ __forceinline__ void mbar_wait(uint32_t bar, uint32_t parity) {
    uint32_t done;
    asm volatile(
        "{\n\t.reg .pred p;\n\t"
        "mbarrier.try_wait.parity.acquire.cluster.shared::cta.b64 p, [%1], %2;\n\t"
        "selp.b32 %0, 1, 0, p;\n\t}"
        : "=r"(done) : "r"(bar), "r"(parity) : "memory");
    if (!done) {
        asm volatile(
            "{\n\t.reg .pred P1;\n\t"
            "WL_%=:\n\t"
            "mbarrier.try_wait.parity.acquire.cluster.shared::cta.b64 P1, [%0], %1, 0x989680;\n\t"
            "@P1 bra.uni WD_%=;\n\t"
            "bra.uni WL_%=;\n\t"
            "WD_%=:\n\t}"
            :: "r"(bar), "r"(parity) : "memory");
    }
}
__device__ __forceinline__ void st_async_f32(uint32_t raddr, float v, uint32_t rbar) {
    asm volatile("st.async.shared::cluster.mbarrier::complete_tx::bytes.b32 [%0], %1, [%2];"
                 :: "r"(raddr), "r"(__float_as_uint(v)), "r"(rbar) : "memory");
}
__device__ __forceinline__ uint32_t mapa32(uint32_t laddr, int p) {
    uint32_t r;
    asm("mapa.shared::cluster.u32 %0, %1, %2;" : "=r"(r) : "r"(laddr), "r"(p));
    return r;
}

// ---------------- device scratch (allocations forbidden) ----------------
__device__ float g_Gx[3ull * NB * SQ * NH];   // [g][b*SQ+t][j]
__device__ float g_hs[(size_t)SQ * NB * NH];  // [t][b][j]

// =====================================================================
// Phase 1: Gx[g][b*SQ+t][j] = sum_i x[b,t,i]*W_g[j,i] + b_g[j]
// =====================================================================
__global__ void __launch_bounds__(256) gemm_pre(
    const float* __restrict__ x,
    const float* __restrict__ Wr, const float* __restrict__ Wz, const float* __restrict__ Wh,
    const float* __restrict__ br, const float* __restrict__ bz, const float* __restrict__ bh)
{
    const int g = blockIdx.z;
    const float* W    = (g == 0) ? Wr : ((g == 1) ? Wz : Wh);
    const float* bias = (g == 0) ? br : ((g == 1) ? bz : bh);

    const int m0 = blockIdx.x * 64;
    const int j0 = blockIdx.y * 64;
    const int tid = threadIdx.x;
    const int tx = tid & 15;
    const int ty = tid >> 4;

    __shared__ __align__(16) float sA[64 * 20];
    __shared__ __align__(16) float sB[16 * 68];

    ull acc[4][2];
    #pragma unroll
    for (int r = 0; r < 4; r++) { acc[r][0] = 0ull; acc[r][1] = 0ull; }

    const int rm = tid >> 2;
    const int kc = tid & 3;

    for (int kt = 0; kt < 16; kt++) {
        float4 a4 = *(const float4*)&x[(size_t)(m0 + rm) * NI + kt * 16 + kc * 4];
        *(float4*)&sA[rm * 20 + kc * 4] = a4;
        float4 b4 = *(const float4*)&W[(size_t)(j0 + rm) * (NI + NH) + kt * 16 + kc * 4];
        sB[(kc * 4 + 0) * 68 + rm] = b4.x;
        sB[(kc * 4 + 1) * 68 + rm] = b4.y;
        sB[(kc * 4 + 2) * 68 + rm] = b4.z;
        sB[(kc * 4 + 3) * 68 + rm] = b4.w;
        __syncthreads();

        #pragma unroll
        for (int kk = 0; kk < 16; kk++) {
            ulonglong2 b2 = *(const ulonglong2*)&sB[kk * 68 + tx * 4];
            #pragma unroll
            for (int r = 0; r < 4; r++) {
                ull ad = f2dup(sA[(ty * 4 + r) * 20 + kk]);
                acc[r][0] = f2fma(ad, b2.x, acc[r][0]);
                acc[r][1] = f2fma(ad, b2.y, acc[r][1]);
            }
        }
        __syncthreads();
    }

    const int jc = j0 + tx * 4;
    float4 bias4 = *(const float4*)&bias[jc];
    #pragma unroll
    for (int r = 0; r < 4; r++) {
        int m = m0 + ty * 4 + r;
        float2 p0 = f2unpack(acc[r][0]);
        float2 p1 = f2unpack(acc[r][1]);
        float4 v;
        v.x = p0.x + bias4.x; v.y = p0.y + bias4.y;
        v.z = p1.x + bias4.z; v.w = p1.y + bias4.w;
        *(float4*)&g_Gx[((size_t)g * (NB * SQ) + m) * NH + jc] = v;
    }
}

// =====================================================================
// Phase 3: out[b][s][o] = sum_h hs[s,b,h]*W_fc[o,h] + b_fc[o]
// =====================================================================
__global__ void __launch_bounds__(256) gemm_fc(
    const float* __restrict__ Wfc, const float* __restrict__ bfc,
    float* __restrict__ out)
{
    const int m0 = blockIdx.x * 64;
    const int j0 = blockIdx.y * 64;
    const int tid = threadIdx.x;
    const int tx = tid & 15;
    const int ty = tid >> 4;

    __shared__ __align__(16) float sA[64 * 20];
    __shared__ __align__(16) float sB[16 * 68];

    ull acc[4][2];
    #pragma unroll
    for (int r = 0; r < 4; r++) { acc[r][0] = 0ull; acc[r][1] = 0ull; }

    const int rm = tid >> 2;
    const int kc = tid & 3;

    for (int kt = 0; kt < 16; kt++) {
        float4 a4 = *(const float4*)&g_hs[(size_t)(m0 + rm) * NH + kt * 16 + kc * 4];
        *(float4*)&sA[rm * 20 + kc * 4] = a4;
        float4 b4 = *(const float4*)&Wfc[(size_t)(j0 + rm) * NH + kt * 16 + kc * 4];
        sB[(kc * 4 + 0) * 68 + rm] = b4.x;
        sB[(kc * 4 + 1) * 68 + rm] = b4.y;
        sB[(kc * 4 + 2) * 68 + rm] = b4.z;
        sB[(kc * 4 + 3) * 68 + rm] = b4.w;
        __syncthreads();

        #pragma unroll
        for (int kk = 0; kk < 16; kk++) {
            ulonglong2 b2 = *(const ulonglong2*)&sB[kk * 68 + tx * 4];
            #pragma unroll
            for (int r = 0; r < 4; r++) {
                ull ad = f2dup(sA[(ty * 4 + r) * 20 + kk]);
                acc[r][0] = f2fma(ad, b2.x, acc[r][0]);
                acc[r][1] = f2fma(ad, b2.y, acc[r][1]);
            }
        }
        __syncthreads();
    }

    const int jc = j0 + tx * 4;
    float4 bias4 = *(const float4*)&bfc[jc];
    #pragma unroll
    for (int r = 0; r < 4; r++) {
        int m = m0 + ty * 4 + r;          // m = s*NB + b
        int b = m & (NB - 1);
        int s = m >> 6;
        float2 p0 = f2unpack(acc[r][0]);
        float2 p1 = f2unpack(acc[r][1]);
        float4 v;
        v.x = p0.x + bias4.x; v.y = p0.y + bias4.y;
        v.z = p1.x + bias4.z; v.w = p1.y + bias4.w;
        *(float4*)&out[((size_t)b * SQ + s) * NO + jc] = v;
    }
}

// =====================================================================
// Phase 2: persistent recurrent kernel. 16 clusters x 8 CTAs, 512 threads.
// Phase A: warps 0-7 compute r, warps 8-15 compute z.
// Phase B: batch-half split for h-tilde. Each (batch,col) row gets exactly
// 16 partials (16 k-slices), reduced over 16 (bug fixed from R3).
// Sync: mbarrier + st.async transaction-counted DSMEM stores.
// =====================================================================
// smem float offsets
#define OW   0                    // weights [3][32][256]      24576 floats
#define OH   24576                // sH  [4][256]               1024
#define ORH  25600                // sRH [4][256]               1024
#define OP   26624                // partials (max 4352 floats)
#define P2_SMEM_BYTES (30976 * 4 + 64)   // + mbarriers
#define BAR_OFF (30976 * 4)

__global__ void __cluster_dims__(8, 1, 1) __launch_bounds__(512, 1)
gru_rec(const float* __restrict__ Wr, const float* __restrict__ Wz,
        const float* __restrict__ Wh, float* __restrict__ hlast)
{
    extern __shared__ float sm[];
    float* sW  = sm + OW;
    float* sH  = sm + OH;
    float* sRH = sm + ORH;
    float* sP  = sm + OP;

    const uint32_t smem_base = (uint32_t)__cvta_generic_to_shared(sm);
    const uint32_t barRH = smem_base + BAR_OFF;
    const uint32_t barH  = smem_base + BAR_OFF + 8;

    const int tid  = threadIdx.x;
    const int rank = blockIdx.x & 7;
    const int b0   = (blockIdx.x >> 3) * 4;
    const int j0   = rank * 32;

    const int s    = tid & 15;          // k-slice (16 slices of 16 k)
    const int q    = (tid >> 4) & 15;   // col pair
    const int gsel = tid >> 8;          // phase A: gate; phase B: batch half
    const int jl0  = 2 * q, jl1 = 2 * q + 1;

    const int rb  = tid >> 5;           // reduction batch (tid<128)
    const int rbc = rb & 3;
    const int rc  = tid & 31;           // reduction local col

    // load recurrent weight slices (h-part: cols 256..511 of W_*)
    for (int idx = tid; idx < 32 * 256; idx += 512) {
        int jj = idx >> 8, k = idx & 255;
        size_t row = (size_t)(j0 + jj) * (NI + NH) + NI + k;
        sW[(0 * 32 + jj) * 256 + k] = Wr[row];
        sW[(1 * 32 + jj) * 256 + k] = Wz[row];
        sW[(2 * 32 + jj) * 256 + k] = Wh[row];
    }
    for (int idx = tid; idx < 1024; idx += 512) sH[idx] = 0.0f;

    if (tid == 0) {
        mbar_init(barRH, 1);
        mbar_init(barH, 1);
        mbar_expect_tx(barRH, 4096);   // phase 0 of barRH, before any sends
    }
    __syncthreads();
    asm volatile("barrier.cluster.arrive.aligned;" ::: "memory");
    asm volatile("barrier.cluster.wait.aligned;"   ::: "memory");

    // DSMEM peer data + barrier addresses (used by tid<128)
    uint32_t rh_peer[8], h_peer[8], brh_peer[8], bh_peer[8];
    {
        uint32_t rha = (uint32_t)__cvta_generic_to_shared(&sRH[rbc * 256 + j0 + rc]);
        uint32_t ha  = (uint32_t)__cvta_generic_to_shared(&sH [rbc * 256 + j0 + rc]);
        #pragma unroll
        for (int p = 0; p < 8; p++) {
            rh_peer[p]  = mapa32(rha, p);
            h_peer[p]   = mapa32(ha, p);
            brh_peer[p] = mapa32(barRH, p);
            bh_peer[p]  = mapa32(barH, p);
        }
    }

    float zv = 0.0f, hv = 0.0f;

    #pragma unroll 1
    for (int t = 0; t < SQ; t++) {
        // prefetch x-part preactivations (consumed at reductions)
        float gxr = 0.f, gxz = 0.f, gxh = 0.f;
        if (tid < 128) {
            size_t base = ((size_t)(b0 + rbc) * SQ + t) * NH + j0 + rc;
            gxr = g_Gx[base];
            gxz = g_Gx[(size_t)(NB * SQ) * NH + base];
            gxh = g_Gx[2ull * (NB * SQ) * NH + base];
        }

        // ---- phase A: gate matvec (gsel=0 -> r, gsel=1 -> z) ----
        {
            ull a0[4], a1[4];
            #pragma unroll
            for (int b = 0; b < 4; b++) { a0[b] = 0ull; a1[b] = 0ull; }
            const float* wb = &sW[(gsel * 32) * 256];
            #pragma unroll
            for (int i = 0; i < 4; i++) {
                int kb = 64 * i + 4 * s;
                ulonglong2 w0 = *(const ulonglong2*)&wb[jl0 * 256 + kb];
                ulonglong2 w1 = *(const ulonglong2*)&wb[jl1 * 256 + kb];
                #pragma unroll
                for (int b = 0; b < 4; b++) {
                    ulonglong2 hb = *(const ulonglong2*)&sH[b * 256 + kb];
                    a0[b] = f2fma(w0.x, hb.x, a0[b]);
                    a0[b] = f2fma(w0.y, hb.y, a0[b]);
                    a1[b] = f2fma(w1.x, hb.x, a1[b]);
                    a1[b] = f2fma(w1.y, hb.y, a1[b]);
                }
            }
            #pragma unroll
            for (int b = 0; b < 4; b++) {
                sP[((gsel * 4 + b) * 32 + jl0) * 17 + s] = f2sum(a0[b]);
                sP[((gsel * 4 + b) * 32 + jl1) * 17 + s] = f2sum(a1[b]);
            }
        }
        __syncthreads();

        if (tid == 0) mbar_expect_tx(barH, 4096);   // before any rank can send h(t)

        if (tid < 128) {
            float vr[16], vz[16];
            #pragma unroll
            for (int u = 0; u < 16; u++) {
                vr[u] = sP[((0 + rbc) * 32 + rc) * 17 + u];
                vz[u] = sP[((4 + rbc) * 32 + rc) * 17 + u];
            }
            #pragma unroll
            for (int st = 8; st >= 1; st >>= 1)
                #pragma unroll
                for (int u = 0; u < st; u++) { vr[u] += vr[u + st]; vz[u] += vz[u + st]; }
            float r = __fdividef(1.0f, 1.0f + __expf(-(vr[0] + gxr)));
            zv      = __fdividef(1.0f, 1.0f + __expf(-(vz[0] + gxz)));
            hv = sH[rbc * 256 + j0 + rc];
            float rh = r * hv;
            #pragma unroll
            for (int p = 0; p < 8; p++) st_async_f32(rh_peer[p], rh, brh_peer[p]);
        }
        mbar_wait(barRH, t & 1);
        if (tid == 0) mbar_expect_tx(barRH, 4096);  // next phase, before h sends

        // ---- phase B: h-tilde matvec (gsel = batch half) ----
        {
            const int bo = gsel * 2;
            ull c0[2], c1[2];
            c0[0] = c0[1] = c1[0] = c1[1] = 0ull;
            const float* wb = &sW[(2 * 32) * 256];
            #pragma unroll
            for (int i = 0; i < 4; i++) {
                int kb = 64 * i + 4 * s;
                ulonglong2 w0 = *(const ulonglong2*)&wb[jl0 * 256 + kb];
                ulonglong2 w1 = *(const ulonglong2*)&wb[jl1 * 256 + kb];
                #pragma unroll
                for (int bb = 0; bb < 2; bb++) {
                    ulonglong2 rh2 = *(const ulonglong2*)&sRH[(bo + bb) * 256 + kb];
                    c0[bb] = f2fma(w0.x, rh2.x, c0[bb]);
                    c0[bb] = f2fma(w0.y, rh2.y, c0[bb]);
                    c1[bb] = f2fma(w1.x, rh2.x, c1[bb]);
                    c1[bb] = f2fma(w1.y, rh2.y, c1[bb]);
                }
            }
            // FIX (R3 bug): each (batch,col) row gets exactly 16 partials at s=0..15
            #pragma unroll
            for (int bb = 0; bb < 2; bb++) {
                sP[((bo + bb) * 32 + jl0) * 17 + s] = f2sum(c0[bb]);
                sP[((bo + bb) * 32 + jl1) * 17 + s] = f2sum(c1[bb]);
            }
        }
        __syncthreads();

        if (tid < 128) {
            float v[16];
            #pragma unroll
            for (int u = 0; u < 16; u++) v[u] = sP[(rbc * 32 + rc) * 17 + u];
            #pragma unroll
            for (int st = 8; st >= 1; st >>= 1)
                #pragma unroll
                for (int u = 0; u < st; u++) v[u] += v[u + st];
            float e  = __expf(2.0f * (v[0] + gxh));
            float ht = 1.0f - __fdividef(2.0f, e + 1.0f);
            float hn = hv + zv * (ht - hv);
            #pragma unroll
            for (int p = 0; p < 8; p++) st_async_f32(h_peer[p], hn, bh_peer[p]);
            g_hs[((size_t)t * NB + (b0 + rbc)) * NH + j0 + rc] = hn;
            if (t == SQ - 1) hlast[(size_t)(b0 + rbc) * NH + j0 + rc] = hn;
        }
        mbar_wait(barH, t & 1);
    }
}

// =====================================================================
extern "C" void kernel_launch(void* const* d_in, const int* in_sizes, int n_in,
                              void* d_out, int out_size) {
    const float* x   = (const float*)d_in[0];
    const float* Wr  = (const float*)d_in[1];
    const float* br  = (const float*)d_in[2];
    const float* Wz  = (const float*)d_in[3];
    const float* bz  = (const float*)d_in[4];
    const float* Wh  = (const float*)d_in[5];
    const float* bh  = (const float*)d_in[6];
    const float* Wfc = (const float*)d_in[7];
    const float* bfc = (const float*)d_in[8];

    float* out   = (float*)d_out;                   // [B, S, O]
    float* hlast = out + (size_t)NB * SQ * NO;      // [B, H]

    cudaFuncSetAttribute(gru_rec, cudaFuncAttributeMaxDynamicSharedMemorySize,
                         P2_SMEM_BYTES);

    gemm_pre<<<dim3((NB * SQ) / 64, NH / 64, 3), 256>>>(x, Wr, Wz, Wh, br, bz, bh);
    gru_rec<<<128, 512, P2_SMEM_BYTES>>>(Wr, Wz, Wh, hlast);
    gemm_fc<<<dim3((SQ * NB) / 64, NO / 64), 256>>>(Wfc, bfc, out);
}

// round 6
// speedup vs baseline: 1.6226x; 1.6226x over previous
#include <cuda_runtime.h>
#include <cstdint>

#define SQ 2048   // sequence length
#define NB 64     // batch
#define NH 256    // hidden
#define NI 256    // input
#define NO 256    // output

typedef unsigned long long ull;

// ---------------- packed f32x2 helpers ----------------
__device__ __forceinline__ ull f2fma(ull a, ull b, ull c) {
    ull d;
    asm("fma.rn.f32x2 %0, %1, %2, %3;" : "=l"(d) : "l"(a), "l"(b), "l"(c));
    return d;
}
__device__ __forceinline__ ull f2dup(float a) {
    ull d; unsigned ai = __float_as_uint(a);
    asm("mov.b64 %0, {%1, %2};" : "=l"(d) : "r"(ai), "r"(ai));
    return d;
}
__device__ __forceinline__ float f2sum(ull a) {
    unsigned lo, hi;
    asm("mov.b64 {%0, %1}, %2;" : "=r"(lo), "=r"(hi) : "l"(a));
    return __uint_as_float(lo) + __uint_as_float(hi);
}
__device__ __forceinline__ float2 f2unpack(ull a) {
    unsigned lo, hi;
    asm("mov.b64 {%0, %1}, %2;" : "=r"(lo), "=r"(hi) : "l"(a));
    return make_float2(__uint_as_float(lo), __uint_as_float(hi));
}

// ---------------- cluster helpers ----------------
__device__ __forceinline__ uint32_t mapa32(uint32_t laddr, int p) {
    uint32_t r;
    asm("mapa.shared::cluster.u32 %0, %1, %2;" : "=r"(r) : "r"(laddr), "r"(p));
    return r;
}
__device__ __forceinline__ void st_cluster_f32(uint32_t raddr, float v) {
    asm volatile("st.shared::cluster.f32 [%0], %1;" :: "r"(raddr), "f"(v) : "memory");
}
__device__ __forceinline__ void cluster_barrier() {
    asm volatile("barrier.cluster.arrive.aligned;" ::: "memory");
    asm volatile("barrier.cluster.wait.aligned;"   ::: "memory");
}

// ---------------- device scratch (allocations forbidden) ----------------
__device__ float g_Gx[3ull * NB * SQ * NH];   // [g][b*SQ+t][j]
__device__ float g_hs[(size_t)SQ * NB * NH];  // [t][b][j]

// =====================================================================
// Phase 1: Gx[g][b*SQ+t][j] = sum_i x[b,t,i]*W_g[j,i] + b_g[j]
// =====================================================================
__global__ void __launch_bounds__(256) gemm_pre(
    const float* __restrict__ x,
    const float* __restrict__ Wr, const float* __restrict__ Wz, const float* __restrict__ Wh,
    const float* __restrict__ br, const float* __restrict__ bz, const float* __restrict__ bh)
{
    const int g = blockIdx.z;
    const float* W    = (g == 0) ? Wr : ((g == 1) ? Wz : Wh);
    const float* bias = (g == 0) ? br : ((g == 1) ? bz : bh);

    const int m0 = blockIdx.x * 64;
    const int j0 = blockIdx.y * 64;
    const int tid = threadIdx.x;
    const int tx = tid & 15;
    const int ty = tid >> 4;

    __shared__ __align__(16) float sA[64 * 20];
    __shared__ __align__(16) float sB[16 * 68];

    ull acc[4][2];
    #pragma unroll
    for (int r = 0; r < 4; r++) { acc[r][0] = 0ull; acc[r][1] = 0ull; }

    const int rm = tid >> 2;
    const int kc = tid & 3;

    for (int kt = 0; kt < 16; kt++) {
        float4 a4 = *(const float4*)&x[(size_t)(m0 + rm) * NI + kt * 16 + kc * 4];
        *(float4*)&sA[rm * 20 + kc * 4] = a4;
        float4 b4 = *(const float4*)&W[(size_t)(j0 + rm) * (NI + NH) + kt * 16 + kc * 4];
        sB[(kc * 4 + 0) * 68 + rm] = b4.x;
        sB[(kc * 4 + 1) * 68 + rm] = b4.y;
        sB[(kc * 4 + 2) * 68 + rm] = b4.z;
        sB[(kc * 4 + 3) * 68 + rm] = b4.w;
        __syncthreads();

        #pragma unroll
        for (int kk = 0; kk < 16; kk++) {
            ulonglong2 b2 = *(const ulonglong2*)&sB[kk * 68 + tx * 4];
            #pragma unroll
            for (int r = 0; r < 4; r++) {
                ull ad = f2dup(sA[(ty * 4 + r) * 20 + kk]);
                acc[r][0] = f2fma(ad, b2.x, acc[r][0]);
                acc[r][1] = f2fma(ad, b2.y, acc[r][1]);
            }
        }
        __syncthreads();
    }

    const int jc = j0 + tx * 4;
    float4 bias4 = *(const float4*)&bias[jc];
    #pragma unroll
    for (int r = 0; r < 4; r++) {
        int m = m0 + ty * 4 + r;
        float2 p0 = f2unpack(acc[r][0]);
        float2 p1 = f2unpack(acc[r][1]);
        float4 v;
        v.x = p0.x + bias4.x; v.y = p0.y + bias4.y;
        v.z = p1.x + bias4.z; v.w = p1.y + bias4.w;
        *(float4*)&g_Gx[((size_t)g * (NB * SQ) + m) * NH + jc] = v;
    }
}

// =====================================================================
// Phase 3: out[b][s][o] = sum_h hs[s,b,h]*W_fc[o,h] + b_fc[o]
// =====================================================================
__global__ void __launch_bounds__(256) gemm_fc(
    const float* __restrict__ Wfc, const float* __restrict__ bfc,
    float* __restrict__ out)
{
    const int m0 = blockIdx.x * 64;
    const int j0 = blockIdx.y * 64;
    const int tid = threadIdx.x;
    const int tx = tid & 15;
    const int ty = tid >> 4;

    __shared__ __align__(16) float sA[64 * 20];
    __shared__ __align__(16) float sB[16 * 68];

    ull acc[4][2];
    #pragma unroll
    for (int r = 0; r < 4; r++) { acc[r][0] = 0ull; acc[r][1] = 0ull; }

    const int rm = tid >> 2;
    const int kc = tid & 3;

    for (int kt = 0; kt < 16; kt++) {
        float4 a4 = *(const float4*)&g_hs[(size_t)(m0 + rm) * NH + kt * 16 + kc * 4];
        *(float4*)&sA[rm * 20 + kc * 4] = a4;
        float4 b4 = *(const float4*)&Wfc[(size_t)(j0 + rm) * NH + kt * 16 + kc * 4];
        sB[(kc * 4 + 0) * 68 + rm] = b4.x;
        sB[(kc * 4 + 1) * 68 + rm] = b4.y;
        sB[(kc * 4 + 2) * 68 + rm] = b4.z;
        sB[(kc * 4 + 3) * 68 + rm] = b4.w;
        __syncthreads();

        #pragma unroll
        for (int kk = 0; kk < 16; kk++) {
            ulonglong2 b2 = *(const ulonglong2*)&sB[kk * 68 + tx * 4];
            #pragma unroll
            for (int r = 0; r < 4; r++) {
                ull ad = f2dup(sA[(ty * 4 + r) * 20 + kk]);
                acc[r][0] = f2fma(ad, b2.x, acc[r][0]);
                acc[r][1] = f2fma(ad, b2.y, acc[r][1]);
            }
        }
        __syncthreads();
    }

    const int jc = j0 + tx * 4;
    float4 bias4 = *(const float4*)&bfc[jc];
    #pragma unroll
    for (int r = 0; r < 4; r++) {
        int m = m0 + ty * 4 + r;          // m = s*NB + b
        int b = m & (NB - 1);
        int s = m >> 6;
        float2 p0 = f2unpack(acc[r][0]);
        float2 p1 = f2unpack(acc[r][1]);
        float4 v;
        v.x = p0.x + bias4.x; v.y = p0.y + bias4.y;
        v.z = p1.x + bias4.z; v.w = p1.y + bias4.w;
        *(float4*)&out[((size_t)b * SQ + s) * NO + jc] = v;
    }
}

// =====================================================================
// Phase 2: persistent recurrent kernel. 16 clusters x 8 CTAs, 512 threads.
// REGISTER-RESIDENT WEIGHTS: thread (c = tid&31, ks = tid>>5) owns
// W_r/W_z/W_h[j0+c][256 + ks*16 .. +16) as 8 f32x2 k-pairs each (48 regs).
// sH/sRH reads are warp-uniform (broadcast, conflict-free).
// Sync: plain st.shared::cluster + barrier.cluster (R2's proven protocol).
// =====================================================================
// smem float offsets
#define OH   0                    // sH  [4][256]   1024 floats
#define ORH  1024                 // sRH [4][256]   1024 floats
#define OP   2048                 // partials [8*32 rows][17] = 4352 floats
#define P2_SMEM_BYTES (6400 * 4)

__global__ void __cluster_dims__(8, 1, 1) __launch_bounds__(512, 1)
gru_rec(const float* __restrict__ Wr, const float* __restrict__ Wz,
        const float* __restrict__ Wh, float* __restrict__ hlast)
{
    extern __shared__ float sm[];
    float* sH  = sm + OH;
    float* sRH = sm + ORH;
    float* sP  = sm + OP;

    const int tid  = threadIdx.x;
    const int rank = blockIdx.x & 7;
    const int b0   = (blockIdx.x >> 3) * 4;
    const int j0   = rank * 32;

    const int c  = tid & 31;    // local output column (matvec)
    const int ks = tid >> 5;    // k-slice (16 slices x 16 k)
    const int k0 = ks * 16;

    const int rb = tid >> 5;    // reduction batch (tid<128)
    const int rc = tid & 31;    // reduction local col

    // ---- load recurrent weight slices into REGISTERS (k-pair packed) ----
    ull wR[8], wZ[8], wH[8];
    {
        size_t row = (size_t)(j0 + c) * (NI + NH) + NI + k0;
        #pragma unroll
        for (int u = 0; u < 8; u++) {
            wR[u] = *(const ull*)&Wr[row + 2 * u];
            wZ[u] = *(const ull*)&Wz[row + 2 * u];
            wH[u] = *(const ull*)&Wh[row + 2 * u];
        }
    }
    for (int idx = tid; idx < 1024; idx += 512) sH[idx] = 0.0f;
    __syncthreads();
    cluster_barrier();

    // DSMEM peer addresses (used by reduction threads tid<128)
    uint32_t rh_peer[8], h_peer[8];
    {
        uint32_t rha = (uint32_t)__cvta_generic_to_shared(&sRH[rb * 256 + j0 + rc]);
        uint32_t ha  = (uint32_t)__cvta_generic_to_shared(&sH [rb * 256 + j0 + rc]);
        #pragma unroll
        for (int p = 0; p < 8; p++) {
            rh_peer[p] = mapa32(rha, p);
            h_peer[p]  = mapa32(ha, p);
        }
    }

    float zv = 0.0f, hv = 0.0f;

    #pragma unroll 1
    for (int t = 0; t < SQ; t++) {
        // prefetch x-part preactivations (consumed at reductions)
        float gxr = 0.f, gxz = 0.f, gxh = 0.f;
        if (tid < 128) {
            size_t base = ((size_t)(b0 + rb) * SQ + t) * NH + j0 + rc;
            gxr = g_Gx[base];
            gxz = g_Gx[(size_t)(NB * SQ) * NH + base];
            gxh = g_Gx[2ull * (NB * SQ) * NH + base];
        }

        // ---- phase A: r,z matvec (weights in regs, sH broadcast reads) ----
        {
            ull aR[4], aZ[4];
            #pragma unroll
            for (int b = 0; b < 4; b++) { aR[b] = 0ull; aZ[b] = 0ull; }
            #pragma unroll
            for (int u = 0; u < 8; u++) {
                int k = k0 + 2 * u;
                ull h0 = *(const ull*)&sH[0 * 256 + k];
                ull h1 = *(const ull*)&sH[1 * 256 + k];
                ull h2 = *(const ull*)&sH[2 * 256 + k];
                ull h3 = *(const ull*)&sH[3 * 256 + k];
                aR[0] = f2fma(wR[u], h0, aR[0]);  aZ[0] = f2fma(wZ[u], h0, aZ[0]);
                aR[1] = f2fma(wR[u], h1, aR[1]);  aZ[1] = f2fma(wZ[u], h1, aZ[1]);
                aR[2] = f2fma(wR[u], h2, aR[2]);  aZ[2] = f2fma(wZ[u], h2, aZ[2]);
                aR[3] = f2fma(wR[u], h3, aR[3]);  aZ[3] = f2fma(wZ[u], h3, aZ[3]);
            }
            #pragma unroll
            for (int b = 0; b < 4; b++) {
                sP[((0 * 4 + b) * 32 + c) * 17 + ks] = f2sum(aR[b]);
                sP[((1 * 4 + b) * 32 + c) * 17 + ks] = f2sum(aZ[b]);
            }
        }
        __syncthreads();

        if (tid < 128) {
            float sr = 0.f, sz = 0.f;
            #pragma unroll
            for (int u = 0; u < 16; u++) {
                sr += sP[((0 * 4 + rb) * 32 + rc) * 17 + u];
                sz += sP[((1 * 4 + rb) * 32 + rc) * 17 + u];
            }
            float r = __fdividef(1.0f, 1.0f + __expf(-(sr + gxr)));
            zv      = __fdividef(1.0f, 1.0f + __expf(-(sz + gxz)));
            hv = sH[rb * 256 + j0 + rc];
            float rh = r * hv;
            #pragma unroll
            for (int p = 0; p < 8; p++) st_cluster_f32(rh_peer[p], rh);
        }
        cluster_barrier();

        // ---- phase B: h-tilde matvec over sRH ----
        {
            ull aH[4];
            #pragma unroll
            for (int b = 0; b < 4; b++) aH[b] = 0ull;
            #pragma unroll
            for (int u = 0; u < 8; u++) {
                int k = k0 + 2 * u;
                ull r0 = *(const ull*)&sRH[0 * 256 + k];
                ull r1 = *(const ull*)&sRH[1 * 256 + k];
                ull r2 = *(const ull*)&sRH[2 * 256 + k];
                ull r3 = *(const ull*)&sRH[3 * 256 + k];
                aH[0] = f2fma(wH[u], r0, aH[0]);
                aH[1] = f2fma(wH[u], r1, aH[1]);
                aH[2] = f2fma(wH[u], r2, aH[2]);
                aH[3] = f2fma(wH[u], r3, aH[3]);
            }
            #pragma unroll
            for (int b = 0; b < 4; b++)
                sP[(b * 32 + c) * 17 + ks] = f2sum(aH[b]);
        }
        __syncthreads();

        if (tid < 128) {
            float sh = 0.f;
            #pragma unroll
            for (int u = 0; u < 16; u++) sh += sP[(rb * 32 + rc) * 17 + u];
            float e  = __expf(2.0f * (sh + gxh));
            float ht = 1.0f - __fdividef(2.0f, e + 1.0f);
            float hn = hv + zv * (ht - hv);
            #pragma unroll
            for (int p = 0; p < 8; p++) st_cluster_f32(h_peer[p], hn);
            g_hs[((size_t)t * NB + (b0 + rb)) * NH + j0 + rc] = hn;
            if (t == SQ - 1) hlast[(size_t)(b0 + rb) * NH + j0 + rc] = hn;
        }
        cluster_barrier();
    }
}

// =====================================================================
extern "C" void kernel_launch(void* const* d_in, const int* in_sizes, int n_in,
                              void* d_out, int out_size) {
    const float* x   = (const float*)d_in[0];
    const float* Wr  = (const float*)d_in[1];
    const float* br  = (const float*)d_in[2];
    const float* Wz  = (const float*)d_in[3];
    const float* bz  = (const float*)d_in[4];
    const float* Wh  = (const float*)d_in[5];
    const float* bh  = (const float*)d_in[6];
    const float* Wfc = (const float*)d_in[7];
    const float* bfc = (const float*)d_in[8];

    float* out   = (float*)d_out;                   // [B, S, O]
    float* hlast = out + (size_t)NB * SQ * NO;      // [B, H]

    cudaFuncSetAttribute(gru_rec, cudaFuncAttributeMaxDynamicSharedMemorySize,
                         P2_SMEM_BYTES);

    gemm_pre<<<dim3((NB * SQ) / 64, NH / 64, 3), 256>>>(x, Wr, Wz, Wh, br, bz, bh);
    gru_rec<<<128, 512, P2_SMEM_BYTES>>>(Wr, Wz, Wh, hlast);
    gemm_fc<<<dim3((SQ * NB) / 64, NO / 64), 256>>>(Wfc, bfc, out);
}